// round 2
// baseline (speedup 1.0000x reference)
#include <cuda_runtime.h>
#include <cstdint>

// MeanAggregatorHead: out[b, :] = (1/K) * sum_k embed_table[neigh_idx[b,k], :]
// B=100000, K=32, N=500000, D=128.
// NOTE: JAX runs with x64 disabled by default -> neigh_idx is int32 on disk.

constexpr int K = 32;
constexpr int D = 128;

__global__ __launch_bounds__(256) void mean_agg_kernel(
    const float* __restrict__ tab,
    const int*   __restrict__ idx,
    float* __restrict__ out,
    int B)
{
    int gtid = blockIdx.x * blockDim.x + threadIdx.x;
    int warp = gtid >> 5;
    int lane = gtid & 31;
    if (warp >= B) return;

    // One coalesced 4B index load per lane; broadcast via shfl in the loop.
    int my_idx = idx[(size_t)warp * K + lane];

    float4 acc = make_float4(0.f, 0.f, 0.f, 0.f);

    #pragma unroll
    for (int k = 0; k < K; ++k) {
        int r = __shfl_sync(0xffffffffu, my_idx, k);
        const float4* row = reinterpret_cast<const float4*>(tab + (size_t)r * D);
        float4 v = __ldg(&row[lane]);   // warp reads one full 512B row, coalesced
        acc.x += v.x; acc.y += v.y; acc.z += v.z; acc.w += v.w;
    }

    const float s = 1.0f / (float)K;
    acc.x *= s; acc.y *= s; acc.z *= s; acc.w *= s;

    reinterpret_cast<float4*>(out + (size_t)warp * D)[lane] = acc;
}

extern "C" void kernel_launch(void* const* d_in, const int* in_sizes, int n_in,
                              void* d_out, int out_size)
{
    // Identify inputs by element count (robust to metadata ordering):
    // embed_table: N*D = 64,000,000 ; neigh_idx: B*K = 3,200,000 ; num_sample: 1
    const float* tab = nullptr;
    const int*   idx = nullptr;
    long long max_sz = -1, mid_sz = -1;
    int ti = 0, ii = 1;
    for (int i = 0; i < n_in; ++i) {
        if (in_sizes[i] > max_sz) { max_sz = in_sizes[i]; ti = i; }
    }
    for (int i = 0; i < n_in; ++i) {
        if (i != ti && in_sizes[i] > mid_sz) { mid_sz = in_sizes[i]; ii = i; }
    }
    tab = (const float*)d_in[ti];
    idx = (const int*)d_in[ii];
    float* out = (float*)d_out;

    int B = out_size / D;            // 100000

    int threads = 256;               // 8 warps/block, 1 node per warp
    long long total_threads = (long long)B * 32;
    int blocks = (int)((total_threads + threads - 1) / threads);

    mean_agg_kernel<<<blocks, threads>>>(tab, idx, out, B);
}

// round 3
// speedup vs baseline: 1.0763x; 1.0763x over previous
#include <cuda_runtime.h>
#include <cstdint>

// MeanAggregatorHead: out[b, :] = (1/K) * sum_k embed_table[neigh_idx[b,k], :]
// B=100000, K=32, N=500000, D=128, fp32 table, int32 indices (JAX x64 off).
//
// Strategy: table-chunked passes. Each kernel launch gathers only rows in
// [lo, hi) so the active table chunk (~128MB) is L2-resident for the whole
// launch -> DRAM traffic drops from ~1.17GB to ~compulsory table reads.
// Pass 0 writes scaled partials to out; pass 1 adds its contribution.

constexpr int K = 32;
constexpr int D = 128;

__global__ __launch_bounds__(256) void mean_agg_pass(
    const float* __restrict__ tab,
    const int*   __restrict__ idx,
    float* __restrict__ out,
    int B, int lo, int hi, int residual)
{
    int gtid = blockIdx.x * blockDim.x + threadIdx.x;
    int warp = gtid >> 5;
    int lane = gtid & 31;
    if (warp >= B) return;

    // One coalesced 4B index load per lane; broadcast via shfl in the loop.
    int my_idx = idx[(size_t)warp * K + lane];

    float4 acc = make_float4(0.f, 0.f, 0.f, 0.f);

    #pragma unroll
    for (int k = 0; k < K; ++k) {
        int r = __shfl_sync(0xffffffffu, my_idx, k);
        // Warp-uniform predicate: whole warp takes or skips the load together.
        if (r >= lo && r < hi) {
            const float4* row = reinterpret_cast<const float4*>(tab + (size_t)r * D);
            float4 v = __ldg(&row[lane]);   // 512B coalesced row per warp
            acc.x += v.x; acc.y += v.y; acc.z += v.z; acc.w += v.w;
        }
    }

    const float s = 1.0f / (float)K;
    acc.x *= s; acc.y *= s; acc.z *= s; acc.w *= s;

    float4* op = reinterpret_cast<float4*>(out + (size_t)warp * D);
    if (residual) {
        float4 p = op[lane];                // pass-0 partial, expected L2-hit
        acc.x += p.x; acc.y += p.y; acc.z += p.z; acc.w += p.w;
    }
    op[lane] = acc;
}

extern "C" void kernel_launch(void* const* d_in, const int* in_sizes, int n_in,
                              void* d_out, int out_size)
{
    // Identify inputs by element count (robust to metadata ordering):
    // embed_table: N*D = 64,000,000 ; neigh_idx: B*K = 3,200,000 ; num_sample: 1
    long long max_sz = -1, mid_sz = -1;
    int ti = 0, ii = 1;
    for (int i = 0; i < n_in; ++i)
        if (in_sizes[i] > max_sz) { max_sz = in_sizes[i]; ti = i; }
    for (int i = 0; i < n_in; ++i)
        if (i != ti && in_sizes[i] > mid_sz) { mid_sz = in_sizes[i]; ii = i; }

    const float* tab = (const float*)d_in[ti];
    const int*   idx = (const int*)d_in[ii];
    float*       out = (float*)d_out;

    int B = out_size / D;                    // 100000
    int N = (int)(max_sz / D);               // 500000 table rows
    int split = N / 2;                       // 128MB chunks

    int threads = 256;
    long long total_threads = (long long)B * 32;
    int blocks = (int)((total_threads + threads - 1) / threads);

    // Pass 0: rows [0, split)    -> out = scaled partial
    mean_agg_pass<<<blocks, threads>>>(tab, idx, out, B, 0, split, 0);
    // Pass 1: rows [split, N)    -> out += scaled partial
    mean_agg_pass<<<blocks, threads>>>(tab, idx, out, B, split, N, 1);
}